// round 16
// baseline (speedup 1.0000x reference)
#include <cuda_runtime.h>

// ---------------- problem constants (max sizes for static scratch) ----------
#define NN   50000
#define EE   800000

// ---------------- device scratch (no allocations allowed) -------------------
static __device__ float g_agg[(size_t)NN * 512];    // agg buffer (layers 1,2) / hcat (layers 0,3)
static __device__ float g_bufA[(size_t)NN * 128];   // layer activations (ping, tf32-rounded)
static __device__ float g_bufB[(size_t)NN * 128];   // layer activations (pong, tf32-rounded)
static __device__ float g_w0[128 * 320];            // layer0 [root|W] K-major, tf32-rounded
static __device__ float g_w3[128 * 320];            // layer3 [root|W] K-major, tf32-rounded
static __device__ float g_w1[640 * 128];            // layer1 [root;W], tf32-rounded
static __device__ float g_w2[640 * 128];            // layer2 [root;W], tf32-rounded
static __device__ float g_q[16 * 64];               // relu(question @ qn_W + qn_b), rounded
static __device__ int   g_cnt4[NN * 4];             // per-(node,relation) in-degree
static __device__ float g_icnt[NN * 4];             // 1/max(cnt,1)
static __device__ int   g_deg[NN];                  // total in-degree
static __device__ int   g_offs[NN + 1];             // CSR row offsets (by dst)
static __device__ int   g_cursor[NN];               // fill cursors
static __device__ int   g_csr[EE];                  // packed (src<<2)|etype, grouped by dst
static __device__ int   g_psum[64];                 // scan partials

// ---------------- helpers ----------------------------------------------------
__device__ __forceinline__ unsigned f2tf(float f) {
    unsigned u;
    asm("cvt.rna.tf32.f32 %0, %1;" : "=r"(u) : "f"(f));
    return u;
}
__device__ __forceinline__ float tfr(float f) { return __uint_as_float(f2tf(f)); }

__device__ __forceinline__ void cp16(void* smem, const void* g) {
    unsigned s = (unsigned)__cvta_generic_to_shared(smem);
    asm volatile("cp.async.ca.shared.global [%0], [%1], 16;\n" :: "r"(s), "l"(g));
}

__device__ __forceinline__ void mma_tf32(float* c, const unsigned* a, const unsigned* b) {
    asm volatile("mma.sync.aligned.m16n8k8.row.col.f32.tf32.tf32.f32 "
                 "{%0,%1,%2,%3}, {%4,%5,%6,%7}, {%8,%9}, {%0,%1,%2,%3};"
                 : "+f"(c[0]), "+f"(c[1]), "+f"(c[2]), "+f"(c[3])
                 : "r"(a[0]), "r"(a[1]), "r"(a[2]), "r"(a[3]),
                   "r"(b[0]), "r"(b[1]));
}

// ---------------- small kernels ---------------------------------------------

__global__ void q_kernel(const float* __restrict__ qe,
                         const float* __restrict__ W,
                         const float* __restrict__ b) {
    int g = blockIdx.x;
    int j = threadIdx.x;
    const float* qr = qe + (size_t)g * 768;
    float s = b[j];
    #pragma unroll 4
    for (int k = 0; k < 768; k++)
        s = fmaf(qr[k], W[(size_t)k * 64 + j], s);
    g_q[g * 64 + j] = tfr(fmaxf(s, 0.f));
}

__global__ void xround_kernel(const float* __restrict__ x, int n) {
    int i = blockIdx.x * 256 + threadIdx.x;
    if (i < n) g_bufB[i] = tfr(x[i]);
}

__global__ void zero_cnt_kernel(int n4) {
    int i = blockIdx.x * 256 + threadIdx.x;
    if (i < n4) g_cnt4[i] = 0;
}

__global__ void count_kernel(const int* __restrict__ dst,
                             const int* __restrict__ et, int E) {
    int e = blockIdx.x * 256 + threadIdx.x;
    if (e < E) atomicAdd(&g_cnt4[dst[e] * 4 + et[e]], 1);
}

__global__ void prep_kernel(int n) {
    int i = blockIdx.x * 256 + threadIdx.x;
    if (i < n) {
        int d = 0;
        #pragma unroll
        for (int r = 0; r < 4; r++) {
            int c = g_cnt4[i * 4 + r];
            d += c;
            g_icnt[i * 4 + r] = 1.f / (float)(c > 0 ? c : 1);
        }
        g_deg[i] = d;
    }
}

__global__ void scan1_kernel(int n) {
    __shared__ int s[1024];
    int t = threadIdx.x;
    int i = blockIdx.x * 1024 + t;
    int v = (i < n) ? g_deg[i] : 0;
    s[t] = v;
    __syncthreads();
    for (int off = 1; off < 1024; off <<= 1) {
        int x = (t >= off) ? s[t - off] : 0;
        __syncthreads();
        s[t] += x;
        __syncthreads();
    }
    if (i < n) g_offs[i] = s[t] - v;
    if (t == 1023) g_psum[blockIdx.x] = s[1023];
}

__global__ void scan2_kernel(int nb) {
    __shared__ int s[64];
    int t = threadIdx.x;
    int v = (t < nb) ? g_psum[t] : 0;
    s[t] = v;
    __syncthreads();
    for (int off = 1; off < 64; off <<= 1) {
        int x = (t >= off) ? s[t - off] : 0;
        __syncthreads();
        s[t] += x;
        __syncthreads();
    }
    if (t < nb) g_psum[t] = s[t] - v;
}

__global__ void scan3_kernel(int n, int E) {
    int t = threadIdx.x;
    int i = blockIdx.x * 1024 + t;
    if (i < n) {
        int o = g_offs[i] + g_psum[blockIdx.x];
        g_offs[i] = o;
        g_cursor[i] = o;
    }
    if (i == 0) g_offs[n] = E;
}

__global__ void fill_kernel(const int* __restrict__ src,
                            const int* __restrict__ dst,
                            const int* __restrict__ et, int E) {
    int e = blockIdx.x * 256 + threadIdx.x;
    if (e < E) {
        int d = dst[e];
        int pos = atomicAdd(&g_cursor[d], 1);
        g_csr[pos] = (src[e] << 2) | et[e];
    }
}

__global__ void qfill_kernel(const int* __restrict__ batch, int n) {
    int t = blockIdx.x * 256 + threadIdx.x;
    if (t < n * 64) {
        int i = t >> 6, j = t & 63;
        g_bufA[(size_t)i * 128 + 64 + j] = g_q[batch[i] * 64 + j];
    }
}

// stage K-major concat weights for OUT=64 layers: W_out[k*320 + c], tf32-rounded
// c<64: root[k,c]; else relation r=(c-64)/64, col o: W[r, k, o]
__global__ void wcat320_kernel(const float* __restrict__ root,
                               const float* __restrict__ W,
                               float* __restrict__ out) {
    int idx = blockIdx.x * 256 + threadIdx.x;
    if (idx < 128 * 320) {
        int k = idx / 320, c = idx - k * 320;
        float v;
        if (c < 64) v = root[k * 64 + c];
        else {
            int cc = c - 64;
            v = W[((cc >> 6) * 128 + k) * 64 + (cc & 63)];
        }
        out[idx] = tfr(v);
    }
}

// stage [root;W] for OUT=128 layers: out[640][128], tf32-rounded
__global__ void wround_kernel(const float* __restrict__ root,
                              const float* __restrict__ W,
                              float* __restrict__ out) {
    int idx = blockIdx.x * 256 + threadIdx.x;
    if (idx < 640 * 128) {
        int k = idx >> 7, o = idx & 127;
        float v = (k < 128) ? root[(size_t)k * 128 + o]
                            : W[(size_t)(k - 128) * 128 + o];
        out[idx] = tfr(v);
    }
}

// ---------------- aggregation in INPUT space (layers 1,2), 2x unroll --------
__global__ void __launch_bounds__(256) aggx_kernel(const float* __restrict__ act,
                                                   int M) {
    int w = (blockIdx.x * 256 + threadIdx.x) >> 5;
    int lane = threadIdx.x & 31;
    if (w >= M) return;
    float a0[4] = {0,0,0,0}, a1[4] = {0,0,0,0};
    float a2[4] = {0,0,0,0}, a3[4] = {0,0,0,0};
    int beg = g_offs[w], end = g_offs[w + 1];
    int e = beg;
    for (; e + 1 < end; e += 2) {
        int p0 = g_csr[e], p1 = g_csr[e + 1];
        float4 v0 = *(const float4*)(act + (size_t)(p0 >> 2) * 128 + lane * 4);
        float4 v1 = *(const float4*)(act + (size_t)(p1 >> 2) * 128 + lane * 4);
        int r0 = p0 & 3;
        if (r0 == 0)      { a0[0]+=v0.x; a0[1]+=v0.y; a0[2]+=v0.z; a0[3]+=v0.w; }
        else if (r0 == 1) { a1[0]+=v0.x; a1[1]+=v0.y; a1[2]+=v0.z; a1[3]+=v0.w; }
        else if (r0 == 2) { a2[0]+=v0.x; a2[1]+=v0.y; a2[2]+=v0.z; a2[3]+=v0.w; }
        else              { a3[0]+=v0.x; a3[1]+=v0.y; a3[2]+=v0.z; a3[3]+=v0.w; }
        int r1 = p1 & 3;
        if (r1 == 0)      { a0[0]+=v1.x; a0[1]+=v1.y; a0[2]+=v1.z; a0[3]+=v1.w; }
        else if (r1 == 1) { a1[0]+=v1.x; a1[1]+=v1.y; a1[2]+=v1.z; a1[3]+=v1.w; }
        else if (r1 == 2) { a2[0]+=v1.x; a2[1]+=v1.y; a2[2]+=v1.z; a2[3]+=v1.w; }
        else              { a3[0]+=v1.x; a3[1]+=v1.y; a3[2]+=v1.z; a3[3]+=v1.w; }
    }
    if (e < end) {
        int p = g_csr[e];
        float4 v = *(const float4*)(act + (size_t)(p >> 2) * 128 + lane * 4);
        int r = p & 3;
        if (r == 0)      { a0[0]+=v.x; a0[1]+=v.y; a0[2]+=v.z; a0[3]+=v.w; }
        else if (r == 1) { a1[0]+=v.x; a1[1]+=v.y; a1[2]+=v.z; a1[3]+=v.w; }
        else if (r == 2) { a2[0]+=v.x; a2[1]+=v.y; a2[2]+=v.z; a2[3]+=v.w; }
        else             { a3[0]+=v.x; a3[1]+=v.y; a3[2]+=v.z; a3[3]+=v.w; }
    }
    const float* icn = g_icnt + w * 4;
    float s0 = icn[0], s1 = icn[1], s2 = icn[2], s3 = icn[3];
    float* o = g_agg + (size_t)w * 512 + lane * 4;
    *(float4*)(o)       = make_float4(tfr(a0[0]*s0), tfr(a0[1]*s0), tfr(a0[2]*s0), tfr(a0[3]*s0));
    *(float4*)(o + 128) = make_float4(tfr(a1[0]*s1), tfr(a1[1]*s1), tfr(a1[2]*s1), tfr(a1[3]*s1));
    *(float4*)(o + 256) = make_float4(tfr(a2[0]*s2), tfr(a2[1]*s2), tfr(a2[2]*s2), tfr(a2[3]*s2));
    *(float4*)(o + 384) = make_float4(tfr(a3[0]*s3), tfr(a3[1]*s3), tfr(a3[2]*s3), tfr(a3[3]*s3));
}

// ---------------- aggregation in OUTPUT space (layers 0,3), 2x unroll -------
// out[w, j] = hcat[w, j] + bias[j] + sum_r icnt[r] * sum_{e in N_r} hcat[src, 64 + r*64 + j]
// lane covers 2 floats (OUT=64); warp gathers 256B contiguous per edge.
__global__ void __launch_bounds__(256) aggh_kernel(const float* __restrict__ hcat,
                                                   const float* __restrict__ bias,
                                                   float* __restrict__ out,
                                                   int ldo, int M, int relu_round) {
    int w = (blockIdx.x * 256 + threadIdx.x) >> 5;
    int lane = threadIdx.x & 31;
    if (w >= M) return;
    float b0v = bias[lane * 2], b1v = bias[lane * 2 + 1];
    const float* hr = hcat + (size_t)w * 320 + lane * 2;
    float a0 = hr[0] + b0v, a1 = hr[1] + b1v;
    const float* icn = g_icnt + w * 4;
    float ic[4] = {icn[0], icn[1], icn[2], icn[3]};
    int beg = g_offs[w], end = g_offs[w + 1];
    int e = beg;
    for (; e + 1 < end; e += 2) {
        int p0 = g_csr[e], p1 = g_csr[e + 1];
        int r0 = p0 & 3, r1 = p1 & 3;
        float2 m0 = *(const float2*)(hcat + (size_t)(p0 >> 2) * 320 + 64 + r0 * 64 + lane * 2);
        float2 m1 = *(const float2*)(hcat + (size_t)(p1 >> 2) * 320 + 64 + r1 * 64 + lane * 2);
        a0 = fmaf(m0.x, ic[r0], a0); a1 = fmaf(m0.y, ic[r0], a1);
        a0 = fmaf(m1.x, ic[r1], a0); a1 = fmaf(m1.y, ic[r1], a1);
    }
    if (e < end) {
        int p = g_csr[e];
        int r = p & 3;
        float2 m = *(const float2*)(hcat + (size_t)(p >> 2) * 320 + 64 + r * 64 + lane * 2);
        a0 = fmaf(m.x, ic[r], a0); a1 = fmaf(m.y, ic[r], a1);
    }
    if (relu_round) { a0 = tfr(fmaxf(a0, 0.f)); a1 = tfr(fmaxf(a1, 0.f)); }
    *(float2*)(out + (size_t)w * ldo + lane * 2) = make_float2(a0, a1);
}

// ---------------- TF32 GEMM K=128 -> hcat[M,320] (layers 0,3) ---------------
// BM=128, BN=64, 3-stage cp.async, 8 chunks. No bias/relu (agg applies).
__global__ void __launch_bounds__(256) gemm320_kernel(
        const float* __restrict__ A0, const float* __restrict__ Wc,
        float* __restrict__ out, int M) {
    __shared__ float As[3][128][20];
    __shared__ float Bs[3][16][72];
    int tid = threadIdx.x;
    int warp = tid >> 5, lane = tid & 31;
    int wm = warp >> 1, wn = warp & 1;
    int lg = lane >> 2, lq = lane & 3;
    int row0 = blockIdx.y * 128, col0 = blockIdx.x * 64;

    float acc[2][4][4];
    #pragma unroll
    for (int t = 0; t < 2; t++)
        #pragma unroll
        for (int j = 0; j < 4; j++)
            #pragma unroll
            for (int v = 0; v < 4; v++) acc[t][j][v] = 0.f;

    int am0 = tid >> 2;
    int am1 = 64 + (tid >> 2);
    int akq = (tid & 3) * 4;
    int bkr = tid >> 4;
    int bn4 = (tid & 15) * 4;
    int r0c = min(row0 + am0, M - 1);
    int r1c = min(row0 + am1, M - 1);

    const int NCHUNK = 8;

    auto issue = [&](int i, int st) {
        int k0 = i * 16;
        cp16(&As[st][am0][akq], A0 + (size_t)r0c * 128 + k0 + akq);
        cp16(&As[st][am1][akq], A0 + (size_t)r1c * 128 + k0 + akq);
        cp16(&Bs[st][bkr][bn4], Wc + (size_t)(k0 + bkr) * 320 + col0 + bn4);
        asm volatile("cp.async.commit_group;\n");
    };

    issue(0, 0);
    issue(1, 1);

    for (int i = 0; i < NCHUNK; i++) {
        if (i + 1 < NCHUNK) asm volatile("cp.async.wait_group 1;\n");
        else                asm volatile("cp.async.wait_group 0;\n");
        __syncthreads();
        int st = i % 3;
        #pragma unroll
        for (int ks = 0; ks < 2; ks++) {
            int kk = ks * 8;
            unsigned a[2][4], b[4][2];
            #pragma unroll
            for (int t = 0; t < 2; t++) {
                int mb = wm * 32 + t * 16;
                a[t][0] = __float_as_uint(As[st][mb + lg][kk + lq]);
                a[t][1] = __float_as_uint(As[st][mb + lg + 8][kk + lq]);
                a[t][2] = __float_as_uint(As[st][mb + lg][kk + lq + 4]);
                a[t][3] = __float_as_uint(As[st][mb + lg + 8][kk + lq + 4]);
            }
            #pragma unroll
            for (int j = 0; j < 4; j++) {
                int nb = wn * 32 + j * 8;
                b[j][0] = __float_as_uint(Bs[st][kk + lq][nb + lg]);
                b[j][1] = __float_as_uint(Bs[st][kk + lq + 4][nb + lg]);
            }
            #pragma unroll
            for (int t = 0; t < 2; t++)
                #pragma unroll
                for (int j = 0; j < 4; j++)
                    mma_tf32(acc[t][j], a[t], b[j]);
        }
        if (i + 2 < NCHUNK) issue(i + 2, (i + 2) % 3);
    }

    #pragma unroll
    for (int t = 0; t < 2; t++) {
        int r0 = row0 + wm * 32 + t * 16 + lg;
        #pragma unroll
        for (int j = 0; j < 4; j++) {
            int cb = col0 + wn * 32 + j * 8 + lq * 2;
            if (r0 < M)
                *(float2*)(out + (size_t)r0 * 320 + cb) =
                    make_float2(acc[t][j][0], acc[t][j][1]);
            if (r0 + 8 < M)
                *(float2*)(out + (size_t)(r0 + 8) * 320 + cb) =
                    make_float2(acc[t][j][2], acc[t][j][3]);
        }
    }
}

// ---------------- TF32 GEMM BN=128, K=640 (layers 1,2): A read once ---------
__global__ void __launch_bounds__(256) gemm128_kernel(
        const float* __restrict__ A0, const float* __restrict__ A1,
        const float* __restrict__ Wc, const float* __restrict__ bias,
        float* __restrict__ out, int M, int relu) {
    __shared__ float As[2][128][20];
    __shared__ float Bs[2][16][136];
    const int OUT = 128;
    int tid = threadIdx.x;
    int warp = tid >> 5, lane = tid & 31;
    int wm = warp >> 1, wn = warp & 1;
    int lg = lane >> 2, lq = lane & 3;
    int row0 = blockIdx.y * 128;

    float acc[2][8][4];
    #pragma unroll
    for (int t = 0; t < 2; t++)
        #pragma unroll
        for (int j = 0; j < 8; j++)
            #pragma unroll
            for (int v = 0; v < 4; v++) acc[t][j][v] = 0.f;

    int am0 = tid >> 2;
    int am1 = 64 + (tid >> 2);
    int akq = (tid & 3) * 4;
    int bkr = tid >> 4;
    int bn4 = (tid & 15) * 4;
    int r0c = min(row0 + am0, M - 1);
    int r1c = min(row0 + am1, M - 1);

    const int NCHUNK = 40;

    auto issue = [&](int i, int st) {
        int k0 = i * 16;
        const float *s0, *s1;
        if (k0 < 128) {
            s0 = A0 + (size_t)r0c * 128 + k0 + akq;
            s1 = A0 + (size_t)r1c * 128 + k0 + akq;
        } else {
            s0 = A1 + (size_t)r0c * 512 + (k0 - 128) + akq;
            s1 = A1 + (size_t)r1c * 512 + (k0 - 128) + akq;
        }
        cp16(&As[st][am0][akq], s0);
        cp16(&As[st][am1][akq], s1);
        const float* bp = Wc + (size_t)(k0 + bkr) * OUT;
        cp16(&Bs[st][bkr][bn4], bp + bn4);
        cp16(&Bs[st][bkr][bn4 + 64], bp + bn4 + 64);
        asm volatile("cp.async.commit_group;\n");
    };

    issue(0, 0);

    for (int i = 0; i < NCHUNK; i++) {
        asm volatile("cp.async.wait_group 0;\n");
        __syncthreads();
        if (i + 1 < NCHUNK) issue(i + 1, (i + 1) & 1);
        int st = i & 1;
        #pragma unroll
        for (int ks = 0; ks < 2; ks++) {
            int kk = ks * 8;
            unsigned a[2][4], b[8][2];
            #pragma unroll
            for (int t = 0; t < 2; t++) {
                int mb = wm * 32 + t * 16;
                a[t][0] = __float_as_uint(As[st][mb + lg][kk + lq]);
                a[t][1] = __float_as_uint(As[st][mb + lg + 8][kk + lq]);
                a[t][2] = __float_as_uint(As[st][mb + lg][kk + lq + 4]);
                a[t][3] = __float_as_uint(As[st][mb + lg + 8][kk + lq + 4]);
            }
            #pragma unroll
            for (int j = 0; j < 8; j++) {
                int nb = wn * 64 + j * 8;
                b[j][0] = __float_as_uint(Bs[st][kk + lq][nb + lg]);
                b[j][1] = __float_as_uint(Bs[st][kk + lq + 4][nb + lg]);
            }
            #pragma unroll
            for (int t = 0; t < 2; t++)
                #pragma unroll
                for (int j = 0; j < 8; j++)
                    mma_tf32(acc[t][j], a[t], b[j]);
        }
    }

    #pragma unroll
    for (int t = 0; t < 2; t++) {
        int r0 = row0 + wm * 32 + t * 16 + lg;
        #pragma unroll
        for (int j = 0; j < 8; j++) {
            int cb = wn * 64 + j * 8 + lq * 2;
            float bv0 = bias[cb], bv1 = bias[cb + 1];
            float v00 = acc[t][j][0] + bv0, v01 = acc[t][j][1] + bv1;
            float v10 = acc[t][j][2] + bv0, v11 = acc[t][j][3] + bv1;
            if (relu) {
                v00 = tfr(fmaxf(v00, 0.f)); v01 = tfr(fmaxf(v01, 0.f));
                v10 = tfr(fmaxf(v10, 0.f)); v11 = tfr(fmaxf(v11, 0.f));
            }
            if (r0 < M)
                *(float2*)(out + (size_t)r0 * OUT + cb) = make_float2(v00, v01);
            if (r0 + 8 < M)
                *(float2*)(out + (size_t)(r0 + 8) * OUT + cb) = make_float2(v10, v11);
        }
    }
}

// ---------------- host driver ------------------------------------------------
extern "C" void kernel_launch(void* const* d_in, const int* in_sizes, int n_in,
                              void* d_out, int out_size) {
    const float* x     = (const float*)d_in[0];
    const int*   ei    = (const int*)d_in[1];
    const int*   ea    = (const int*)d_in[2];
    const int*   batch = (const int*)d_in[3];
    const float* qe    = (const float*)d_in[4];
    const float* qnW   = (const float*)d_in[5];
    const float* qnb   = (const float*)d_in[6];
    const float* W0    = (const float*)d_in[7];
    const float* root0 = (const float*)d_in[8];
    const float* b0    = (const float*)d_in[9];
    const float* W1    = (const float*)d_in[10];
    const float* root1 = (const float*)d_in[11];
    const float* b1    = (const float*)d_in[12];
    const float* W2    = (const float*)d_in[13];
    const float* root2 = (const float*)d_in[14];
    const float* b2    = (const float*)d_in[15];
    const float* W3    = (const float*)d_in[16];
    const float* root3 = (const float*)d_in[17];
    const float* b3    = (const float*)d_in[18];

    int N = in_sizes[0] / 128;
    int E = in_sizes[2];
    const int* src = ei;
    const int* dst = ei + E;

    float *bufA, *bufB, *agg, *w0, *w1, *w2, *w3;
    cudaGetSymbolAddress((void**)&bufA, g_bufA);
    cudaGetSymbolAddress((void**)&bufB, g_bufB);
    cudaGetSymbolAddress((void**)&agg, g_agg);
    cudaGetSymbolAddress((void**)&w0, g_w0);
    cudaGetSymbolAddress((void**)&w1, g_w1);
    cudaGetSymbolAddress((void**)&w2, g_w2);
    cudaGetSymbolAddress((void**)&w3, g_w3);

    int nb1024 = (N + 1023) / 1024;

    // --- structure precompute + weight staging (all up front) ---
    q_kernel<<<16, 64>>>(qe, qnW, qnb);
    xround_kernel<<<(N * 128 + 255) / 256, 256>>>(x, N * 128);
    zero_cnt_kernel<<<(N * 4 + 255) / 256, 256>>>(N * 4);
    count_kernel<<<(E + 255) / 256, 256>>>(dst, ea, E);
    prep_kernel<<<(N + 255) / 256, 256>>>(N);
    scan1_kernel<<<nb1024, 1024>>>(N);
    scan2_kernel<<<1, 64>>>(nb1024);
    scan3_kernel<<<nb1024, 1024>>>(N, E);
    fill_kernel<<<(E + 255) / 256, 256>>>(src, dst, ea, E);
    wcat320_kernel<<<(128 * 320 + 255) / 256, 256>>>(root0, W0, w0);
    wcat320_kernel<<<(128 * 320 + 255) / 256, 256>>>(root3, W3, w3);
    wround_kernel<<<(640 * 128 + 255) / 256, 256>>>(root1, W1, w1);
    wround_kernel<<<(640 * 128 + 255) / 256, 256>>>(root2, W2, w2);

    int nby = (N + 127) / 128;
    int agg_blocks = (N + 7) / 8;

    // --- layer 0 (transform-first): hcat = x @ [root0|W0]; agg -> bufA[:,0:64]
    gemm320_kernel<<<dim3(5, nby), 256>>>(bufB, w0, agg, N);
    aggh_kernel<<<agg_blocks, 256>>>(agg, b0, bufA, 128, N, 1);
    qfill_kernel<<<(N * 64 + 255) / 256, 256>>>(batch, N);

    // --- layer 1 (gather-first): agg <- bufA neighbors; gemm -> bufB ---
    aggx_kernel<<<agg_blocks, 256>>>(bufA, N);
    gemm128_kernel<<<dim3(1, nby), 256>>>(bufA, agg, w1, b1, bufB, N, 1);

    // --- layer 2 (gather-first): agg <- bufB neighbors; gemm -> bufA ---
    aggx_kernel<<<agg_blocks, 256>>>(bufB, N);
    gemm128_kernel<<<dim3(1, nby), 256>>>(bufB, agg, w2, b2, bufA, N, 1);

    // --- layer 3 (transform-first): hcat = bufA @ [root3|W3]; agg -> d_out ---
    gemm320_kernel<<<dim3(5, nby), 256>>>(bufA, w3, agg, N);
    aggh_kernel<<<agg_blocks, 256>>>(agg, b3, (float*)d_out, 64, N, 0);
}